// round 2
// baseline (speedup 1.0000x reference)
#include <cuda_runtime.h>
#include <math.h>

#define Bq 16
#define Sq 1024
#define Eq 256
#define Hq 256
#define FHq 512
#define WSq 5
#define Nq (Bq*Sq)          /* 16384 sequences/positions */
#define G4 (4*Hq)           /* 1024 gate width */
#define H2 (2*Hq)           /* 512 concat width */

// ---------------- scratch (static device arrays; no allocation) ----------------
__device__ float g_emb[(size_t)Nq * Eq];            // 16 MB
__device__ float g_Z[2ull * Nq * G4];               // 134 MB  (fwd, bwd input projections incl. bias)
__device__ float g_WhhT[2 * Hq * G4];               // 2 MB    [dir][k][u][gate] interleaved
__device__ float g_bsum[2 * G4];                    // bih+bhh per dir
__device__ float g_Hcat[(size_t)Nq * H2];           // 33 MB   leaky(concat h)
__device__ float g_F1[(size_t)Nq * FHq];            // 33 MB   leaky(fc1 out)

__device__ __forceinline__ float sigf(float x) { return 1.f / (1.f + __expf(-x)); }

// ---------------- embedding gather (embed[0] forced to 0) ----------------
__global__ void embed_kernel(const int* __restrict__ x, const float* __restrict__ embed) {
    int row = blockIdx.x;
    int v = x[row];
    float val = (v == 0) ? 0.f : embed[(size_t)v * Eq + threadIdx.x];
    g_emb[(size_t)row * Eq + threadIdx.x] = val;
}

// ---------------- prep: Whh transpose+gate-interleave, bias sums ----------------
// g_WhhT[dir][(k*256+u)*4 + g] = Whh_dir[g*256+u][k]
__global__ void prep_kernel(const float* __restrict__ Whh_f, const float* __restrict__ Whh_b,
                            const float* __restrict__ bih_f, const float* __restrict__ bhh_f,
                            const float* __restrict__ bih_b, const float* __restrict__ bhh_b) {
    int dir = blockIdx.y;
    int k = blockIdx.x;        // 0..255
    int u = threadIdx.x;       // 0..255
    const float* W = dir ? Whh_b : Whh_f;
    float* dst = g_WhhT + dir * (Hq * G4);
#pragma unroll
    for (int g = 0; g < 4; g++)
        dst[(k * Hq + u) * 4 + g] = W[(size_t)(g * Hq + u) * Hq + k];
    if (k < 4) {
        int j = k * 256 + u;
        const float* b1 = dir ? bih_b : bih_f;
        const float* b2 = dir ? bhh_b : bhh_f;
        g_bsum[dir * G4 + j] = b1[j] + b2[j];
    }
}

// ---------------- generic GEMM: C[M][N] = act(A[M][K] @ W[N][K]^T + bias[N]) ----------------
// BM=BN=128, BK=8, 256 threads, 8x8 microtile
template <bool LEAKY>
__global__ void __launch_bounds__(256) gemm_kernel(
    const float* __restrict__ A, const float* __restrict__ W,
    const float* __restrict__ bias, float* __restrict__ C,
    int M, int N, int K) {
    __shared__ float As[8][128];
    __shared__ float Ws[8][128];
    int tid = threadIdx.x;
    int bm = blockIdx.y * 128;
    int bn = blockIdx.x * 128;
    int tx = tid & 15, ty = tid >> 4;

    float acc[8][8];
#pragma unroll
    for (int i = 0; i < 8; i++)
#pragma unroll
        for (int j = 0; j < 8; j++) acc[i][j] = 0.f;

    int lr = tid >> 1;            // 0..127
    int lk = (tid & 1) * 4;       // 0 or 4
    const float* Aptr = A + (size_t)(bm + lr) * K + lk;
    const float* Wptr = W + (size_t)(bn + lr) * K + lk;

    for (int k0 = 0; k0 < K; k0 += 8) {
        float4 a4 = *(const float4*)(Aptr + k0);
        float4 w4 = *(const float4*)(Wptr + k0);
        __syncthreads();
        As[lk + 0][lr] = a4.x; As[lk + 1][lr] = a4.y; As[lk + 2][lr] = a4.z; As[lk + 3][lr] = a4.w;
        Ws[lk + 0][lr] = w4.x; Ws[lk + 1][lr] = w4.y; Ws[lk + 2][lr] = w4.z; Ws[lk + 3][lr] = w4.w;
        __syncthreads();
#pragma unroll
        for (int k = 0; k < 8; k++) {
            float4 a0 = *(const float4*)&As[k][ty * 8];
            float4 a1 = *(const float4*)&As[k][ty * 8 + 4];
            float4 w0 = *(const float4*)&Ws[k][tx * 8];
            float4 w1 = *(const float4*)&Ws[k][tx * 8 + 4];
            float ar[8] = {a0.x, a0.y, a0.z, a0.w, a1.x, a1.y, a1.z, a1.w};
            float wr[8] = {w0.x, w0.y, w0.z, w0.w, w1.x, w1.y, w1.z, w1.w};
#pragma unroll
            for (int i = 0; i < 8; i++)
#pragma unroll
                for (int j = 0; j < 8; j++) acc[i][j] += ar[i] * wr[j];
        }
    }

#pragma unroll
    for (int i = 0; i < 8; i++) {
        size_t rowoff = (size_t)(bm + ty * 8 + i) * N + bn;
#pragma unroll
        for (int j = 0; j < 8; j++) {
            float v = acc[i][j] + bias[bn + tx * 8 + j];
            if (LEAKY) v = (v > 0.f) ? v : 0.01f * v;
            C[rowoff + tx * 8 + j] = v;
        }
    }
}

// ---------------- fused bidirectional windowed LSTM ----------------
// block = 32 consecutive positions (same batch), thread = hidden unit u.
// h in smem (broadcast), c in registers, gates fully in registers (WhhT gate-interleaved).
__global__ void __launch_bounds__(256, 1) lstm_kernel() {
    __shared__ float sh_h[32][Hq];      // 32 KB
    const int u = threadIdx.x;
    const int n0 = blockIdx.x * 32;
    const int s0 = n0 & (Sq - 1);
    const int bbase = n0 - s0;          // batch row base

    for (int dir = 0; dir < 2; dir++) {
        const float* Zd = g_Z + (size_t)dir * Nq * G4;
        const float* Wd = g_WhhT + dir * (Hq * G4);
        float b[4];
#pragma unroll
        for (int g = 0; g < 4; g++) b[g] = g_bsum[dir * G4 + g * Hq + u];

        float c[32];
#pragma unroll
        for (int m = 0; m < 32; m++) { c[m] = 0.f; sh_h[m][u] = 0.f; }
        __syncthreads();

        for (int step = 0; step < 6; step++) {
            float acc[32][4];
#pragma unroll
            for (int m = 0; m < 32; m++) {
                int p = dir == 0 ? (s0 + m - WSq + step) : (s0 + m + WSq - step);
                bool valid = (unsigned)p < (unsigned)Sq;
                const float* zr = Zd + (size_t)(bbase + p) * G4 + u;
#pragma unroll
                for (int g = 0; g < 4; g++)
                    acc[m][g] = valid ? zr[g * Hq] : b[g];
            }
            // hidden GEMM: acc[m][:] += h[m][:] @ Whh^T  (gate-interleaved weights)
#pragma unroll 2
            for (int k = 0; k < Hq; k++) {
                float4 w = *(const float4*)(Wd + (k * Hq + u) * 4);
#pragma unroll
                for (int m = 0; m < 32; m++) {
                    float hm = sh_h[m][k];
                    acc[m][0] += hm * w.x;
                    acc[m][1] += hm * w.y;
                    acc[m][2] += hm * w.z;
                    acc[m][3] += hm * w.w;
                }
            }
            __syncthreads();
#pragma unroll
            for (int m = 0; m < 32; m++) {
                float ig = sigf(acc[m][0]);
                float fg = sigf(acc[m][1]);
                float gg = tanhf(acc[m][2]);
                float og = sigf(acc[m][3]);
                c[m] = fg * c[m] + ig * gg;
                float hv = og * tanhf(c[m]);
                sh_h[m][u] = hv;
                if (step == 5) {
                    float lv = (hv > 0.f) ? hv : 0.01f * hv;
                    g_Hcat[(size_t)(n0 + m) * H2 + dir * Hq + u] = lv;
                }
            }
            __syncthreads();
        }
    }
}

// ---------------- fc2: per-row dot(512) + sigmoid ----------------
__global__ void fc2_kernel(const float* __restrict__ w2, const float* __restrict__ b2,
                           float* __restrict__ out) {
    int warp = threadIdx.x >> 5, lane = threadIdx.x & 31;
    int row = blockIdx.x * 8 + warp;
    const float* r = g_F1 + (size_t)row * FHq;
    float s = 0.f;
#pragma unroll
    for (int c = lane; c < FHq; c += 32) s += r[c] * w2[c];
#pragma unroll
    for (int o = 16; o; o >>= 1) s += __shfl_xor_sync(0xffffffffu, s, o);
    if (lane == 0) out[row] = 1.f / (1.f + __expf(-(s + b2[0])));
}

// ---------------- launch ----------------
extern "C" void kernel_launch(void* const* d_in, const int* in_sizes, int n_in,
                              void* d_out, int out_size) {
    const int*   x     = (const int*)d_in[0];
    const float* embed = (const float*)d_in[1];
    const float* Wih_f = (const float*)d_in[2];
    const float* Whh_f = (const float*)d_in[3];
    const float* bih_f = (const float*)d_in[4];
    const float* bhh_f = (const float*)d_in[5];
    const float* Wih_b = (const float*)d_in[6];
    const float* Whh_b = (const float*)d_in[7];
    const float* bih_b = (const float*)d_in[8];
    const float* bhh_b = (const float*)d_in[9];
    const float* fc1_w = (const float*)d_in[10];
    const float* fc1_b = (const float*)d_in[11];
    const float* fc2_w = (const float*)d_in[12];
    const float* fc2_b = (const float*)d_in[13];
    float* out = (float*)d_out;

    float *p_emb, *p_Z, *p_bsum, *p_Hcat, *p_F1;
    cudaGetSymbolAddress((void**)&p_emb,  g_emb);
    cudaGetSymbolAddress((void**)&p_Z,    g_Z);
    cudaGetSymbolAddress((void**)&p_bsum, g_bsum);
    cudaGetSymbolAddress((void**)&p_Hcat, g_Hcat);
    cudaGetSymbolAddress((void**)&p_F1,   g_F1);

    embed_kernel<<<Nq, 256>>>(x, embed);
    prep_kernel<<<dim3(Hq, 2), 256>>>(Whh_f, Whh_b, bih_f, bhh_f, bih_b, bhh_b);

    // input projections (bias folded in): Z = emb @ Wih^T + (bih+bhh)
    gemm_kernel<false><<<dim3(G4 / 128, Nq / 128), 256>>>(p_emb, Wih_f, p_bsum,      p_Z,                     Nq, G4, Eq);
    gemm_kernel<false><<<dim3(G4 / 128, Nq / 128), 256>>>(p_emb, Wih_b, p_bsum + G4, p_Z + (size_t)Nq * G4,   Nq, G4, Eq);

    lstm_kernel<<<Nq / 32, 256>>>();

    // fc1 with leaky output (leaky on Hcat already applied at store)
    gemm_kernel<true><<<dim3(FHq / 128, Nq / 128), 256>>>(p_Hcat, fc1_w, fc1_b, p_F1, Nq, FHq, H2);

    fc2_kernel<<<Nq / 8, 256>>>(fc2_w, fc2_b, out);
}

// round 3
// speedup vs baseline: 1.0043x; 1.0043x over previous
#include <cuda_runtime.h>
#include <math.h>

#define Bq 16
#define Sq 1024
#define Eq 256
#define Hq 256
#define FHq 512
#define WSq 5
#define Nq (Bq*Sq)          /* 16384 sequences/positions */
#define G4 (4*Hq)           /* 1024 gate width */
#define H2 (2*Hq)           /* 512 concat width */

// ---------------- scratch (static device arrays; no allocation) ----------------
__device__ float g_emb[(size_t)Nq * Eq];            // 16 MB
__device__ float g_Z[2ull * Nq * G4];               // 134 MB  (fwd, bwd input projections incl. bias)
__device__ float g_WhhT[2 * Hq * G4];               // 2 MB    [dir][k][u][gate] interleaved
__device__ float g_bsum[2 * G4];                    // bih+bhh per dir
__device__ float g_Hcat[(size_t)Nq * H2];           // 33 MB   leaky(concat h)
__device__ float g_F1[(size_t)Nq * FHq];            // 33 MB   leaky(fc1 out)

__device__ __forceinline__ float sigf(float x) { return 1.f / (1.f + __expf(-x)); }

// ---------------- embedding gather (embed[0] forced to 0) ----------------
__global__ void embed_kernel(const int* __restrict__ x, const float* __restrict__ embed) {
    int row = blockIdx.x;
    int v = x[row];
    float val = (v == 0) ? 0.f : embed[(size_t)v * Eq + threadIdx.x];
    g_emb[(size_t)row * Eq + threadIdx.x] = val;
}

// ---------------- prep: Whh transpose+gate-interleave, bias sums ----------------
// g_WhhT[dir][(k*256+u)*4 + g] = Whh_dir[g*256+u][k]
__global__ void prep_kernel(const float* __restrict__ Whh_f, const float* __restrict__ Whh_b,
                            const float* __restrict__ bih_f, const float* __restrict__ bhh_f,
                            const float* __restrict__ bih_b, const float* __restrict__ bhh_b) {
    int dir = blockIdx.y;
    int k = blockIdx.x;        // 0..255
    int u = threadIdx.x;       // 0..255
    const float* W = dir ? Whh_b : Whh_f;
    float* dst = g_WhhT + dir * (Hq * G4);
#pragma unroll
    for (int g = 0; g < 4; g++)
        dst[(k * Hq + u) * 4 + g] = W[(size_t)(g * Hq + u) * Hq + k];
    if (k < 4) {
        int j = k * 256 + u;
        const float* b1 = dir ? bih_b : bih_f;
        const float* b2 = dir ? bhh_b : bhh_f;
        g_bsum[dir * G4 + j] = b1[j] + b2[j];
    }
}

// ---------------- generic GEMM: C[M][N] = act(A[M][K] @ W[N][K]^T + bias[N]) ----------------
// BM=BN=128, BK=8, 256 threads, 8x8 microtile
template <bool LEAKY>
__global__ void __launch_bounds__(256) gemm_kernel(
    const float* __restrict__ A, const float* __restrict__ W,
    const float* __restrict__ bias, float* __restrict__ C,
    int M, int N, int K) {
    __shared__ float As[8][128];
    __shared__ float Ws[8][128];
    int tid = threadIdx.x;
    int bm = blockIdx.y * 128;
    int bn = blockIdx.x * 128;
    int tx = tid & 15, ty = tid >> 4;

    float acc[8][8];
#pragma unroll
    for (int i = 0; i < 8; i++)
#pragma unroll
        for (int j = 0; j < 8; j++) acc[i][j] = 0.f;

    int lr = tid >> 1;            // 0..127
    int lk = (tid & 1) * 4;       // 0 or 4
    const float* Aptr = A + (size_t)(bm + lr) * K + lk;
    const float* Wptr = W + (size_t)(bn + lr) * K + lk;

    for (int k0 = 0; k0 < K; k0 += 8) {
        float4 a4 = *(const float4*)(Aptr + k0);
        float4 w4 = *(const float4*)(Wptr + k0);
        __syncthreads();
        As[lk + 0][lr] = a4.x; As[lk + 1][lr] = a4.y; As[lk + 2][lr] = a4.z; As[lk + 3][lr] = a4.w;
        Ws[lk + 0][lr] = w4.x; Ws[lk + 1][lr] = w4.y; Ws[lk + 2][lr] = w4.z; Ws[lk + 3][lr] = w4.w;
        __syncthreads();
#pragma unroll
        for (int k = 0; k < 8; k++) {
            float4 a0 = *(const float4*)&As[k][ty * 8];
            float4 a1 = *(const float4*)&As[k][ty * 8 + 4];
            float4 w0 = *(const float4*)&Ws[k][tx * 8];
            float4 w1 = *(const float4*)&Ws[k][tx * 8 + 4];
            float ar[8] = {a0.x, a0.y, a0.z, a0.w, a1.x, a1.y, a1.z, a1.w};
            float wr[8] = {w0.x, w0.y, w0.z, w0.w, w1.x, w1.y, w1.z, w1.w};
#pragma unroll
            for (int i = 0; i < 8; i++)
#pragma unroll
                for (int j = 0; j < 8; j++) acc[i][j] += ar[i] * wr[j];
        }
    }

#pragma unroll
    for (int i = 0; i < 8; i++) {
        size_t rowoff = (size_t)(bm + ty * 8 + i) * N + bn;
#pragma unroll
        for (int j = 0; j < 8; j++) {
            float v = acc[i][j] + bias[bn + tx * 8 + j];
            if (LEAKY) v = (v > 0.f) ? v : 0.01f * v;
            C[rowoff + tx * 8 + j] = v;
        }
    }
}

// ---------------- fused bidirectional windowed LSTM ----------------
// block = 32 consecutive positions (same batch), thread = hidden unit u.
// h in smem (broadcast), c in registers, gates fully in registers (WhhT gate-interleaved).
__global__ void __launch_bounds__(256, 1) lstm_kernel() {
    __shared__ float sh_h[32][Hq];      // 32 KB
    const int u = threadIdx.x;
    const int n0 = blockIdx.x * 32;
    const int s0 = n0 & (Sq - 1);
    const int bbase = n0 - s0;          // batch row base

    for (int dir = 0; dir < 2; dir++) {
        const float* Zd = g_Z + (size_t)dir * Nq * G4;
        const float* Wd = g_WhhT + dir * (Hq * G4);
        float b[4];
#pragma unroll
        for (int g = 0; g < 4; g++) b[g] = g_bsum[dir * G4 + g * Hq + u];

        float c[32];
#pragma unroll
        for (int m = 0; m < 32; m++) { c[m] = 0.f; sh_h[m][u] = 0.f; }
        __syncthreads();

        for (int step = 0; step < 6; step++) {
            float acc[32][4];
#pragma unroll
            for (int m = 0; m < 32; m++) {
                int p = dir == 0 ? (s0 + m - WSq + step) : (s0 + m + WSq - step);
                bool valid = (unsigned)p < (unsigned)Sq;
                const float* zr = Zd + (size_t)(bbase + p) * G4 + u;
#pragma unroll
                for (int g = 0; g < 4; g++)
                    acc[m][g] = valid ? zr[g * Hq] : b[g];
            }
            // hidden GEMM: acc[m][:] += h[m][:] @ Whh^T  (gate-interleaved weights)
#pragma unroll 2
            for (int k = 0; k < Hq; k++) {
                float4 w = *(const float4*)(Wd + (k * Hq + u) * 4);
#pragma unroll
                for (int m = 0; m < 32; m++) {
                    float hm = sh_h[m][k];
                    acc[m][0] += hm * w.x;
                    acc[m][1] += hm * w.y;
                    acc[m][2] += hm * w.z;
                    acc[m][3] += hm * w.w;
                }
            }
            __syncthreads();
#pragma unroll
            for (int m = 0; m < 32; m++) {
                float ig = sigf(acc[m][0]);
                float fg = sigf(acc[m][1]);
                float gg = tanhf(acc[m][2]);
                float og = sigf(acc[m][3]);
                c[m] = fg * c[m] + ig * gg;
                float hv = og * tanhf(c[m]);
                sh_h[m][u] = hv;
                if (step == 5) {
                    float lv = (hv > 0.f) ? hv : 0.01f * hv;
                    g_Hcat[(size_t)(n0 + m) * H2 + dir * Hq + u] = lv;
                }
            }
            __syncthreads();
        }
    }
}

// ---------------- fc2: per-row dot(512) + sigmoid ----------------
__global__ void fc2_kernel(const float* __restrict__ w2, const float* __restrict__ b2,
                           float* __restrict__ out) {
    int warp = threadIdx.x >> 5, lane = threadIdx.x & 31;
    int row = blockIdx.x * 8 + warp;
    const float* r = g_F1 + (size_t)row * FHq;
    float s = 0.f;
#pragma unroll
    for (int c = lane; c < FHq; c += 32) s += r[c] * w2[c];
#pragma unroll
    for (int o = 16; o; o >>= 1) s += __shfl_xor_sync(0xffffffffu, s, o);
    if (lane == 0) out[row] = 1.f / (1.f + __expf(-(s + b2[0])));
}

// ---------------- launch ----------------
extern "C" void kernel_launch(void* const* d_in, const int* in_sizes, int n_in,
                              void* d_out, int out_size) {
    const int*   x     = (const int*)d_in[0];
    const float* embed = (const float*)d_in[1];
    const float* Wih_f = (const float*)d_in[2];
    const float* Whh_f = (const float*)d_in[3];
    const float* bih_f = (const float*)d_in[4];
    const float* bhh_f = (const float*)d_in[5];
    const float* Wih_b = (const float*)d_in[6];
    const float* Whh_b = (const float*)d_in[7];
    const float* bih_b = (const float*)d_in[8];
    const float* bhh_b = (const float*)d_in[9];
    const float* fc1_w = (const float*)d_in[10];
    const float* fc1_b = (const float*)d_in[11];
    const float* fc2_w = (const float*)d_in[12];
    const float* fc2_b = (const float*)d_in[13];
    float* out = (float*)d_out;

    float *p_emb, *p_Z, *p_bsum, *p_Hcat, *p_F1;
    cudaGetSymbolAddress((void**)&p_emb,  g_emb);
    cudaGetSymbolAddress((void**)&p_Z,    g_Z);
    cudaGetSymbolAddress((void**)&p_bsum, g_bsum);
    cudaGetSymbolAddress((void**)&p_Hcat, g_Hcat);
    cudaGetSymbolAddress((void**)&p_F1,   g_F1);

    embed_kernel<<<Nq, 256>>>(x, embed);
    prep_kernel<<<dim3(Hq, 2), 256>>>(Whh_f, Whh_b, bih_f, bhh_f, bih_b, bhh_b);

    // input projections (bias folded in): Z = emb @ Wih^T + (bih+bhh)
    gemm_kernel<false><<<dim3(G4 / 128, Nq / 128), 256>>>(p_emb, Wih_f, p_bsum,      p_Z,                     Nq, G4, Eq);
    gemm_kernel<false><<<dim3(G4 / 128, Nq / 128), 256>>>(p_emb, Wih_b, p_bsum + G4, p_Z + (size_t)Nq * G4,   Nq, G4, Eq);

    lstm_kernel<<<Nq / 32, 256>>>();

    // fc1 with leaky output (leaky on Hcat already applied at store)
    gemm_kernel<true><<<dim3(FHq / 128, Nq / 128), 256>>>(p_Hcat, fc1_w, fc1_b, p_F1, Nq, FHq, H2);

    fc2_kernel<<<Nq / 8, 256>>>(fc2_w, fc2_b, out);
}